// round 1
// baseline (speedup 1.0000x reference)
#include <cuda_runtime.h>

// Problem constants (from reference):
//   B=64, LP=256, LH=384, D=512, VOCAB=50000
// Inputs (metadata order):
//   d_in[0] inputs_pre  int32 [64,256]
//   d_in[1] inputs_hyp  int32 [64,384]
//   d_in[2] content_mask      (unused, all ones)
//   d_in[3] cit_content_mask  (unused, all ones)
//   d_in[4] emb  float32 [50000,512]
//   d_in[5] W1   float32 [2048,512]
//   d_in[6] b1   float32 [512]
//   d_in[7] W2   float32 [512,1]
//   d_in[8] b2   float32 [1]
// Output: float32 [64,1]
//
// Key identity: softmax(·,axis=1) columns sum to 1 over LP and
// softmax(·,axis=2) rows sum to 1 over LH, so
//   sum_p pre_att = sum_h hyp   and   sum_h hyp_att = sum_p pre.
// Hence pre_hyp[b] = [S_pre, S_hyp, S_hyp, S_pre] with
//   S_pre[b] = sum_p emb[inputs_pre[b,p]], S_hyp[b] = sum_h emb[inputs_hyp[b,h]].
// The entire attention block cancels exactly.

#define BB   64
#define LPP  256
#define LHH  384
#define DD   512

// Scratch (no allocations allowed)
__device__ float g_S[BB * 2 * DD];        // [b][seg][d]: seg0 = S_pre, seg1 = S_hyp
__device__ float g_Wf[2 * DD * DD];       // folded W1: [1024, 512]
__device__ float g_H[BB * DD];            // hidden relu output [64, 512]

// ---------------------------------------------------------------------------
// Kernel 1: embedding gather + sum.  grid (B, 2), block 512 threads.
// Each block sums L rows (256 or 384) of 512 floats; thread d owns dim d.
// ---------------------------------------------------------------------------
__global__ __launch_bounds__(512) void k_gather_sum(
    const int* __restrict__ idx_pre,
    const int* __restrict__ idx_hyp,
    const float* __restrict__ emb)
{
    const int b   = blockIdx.x;
    const int seg = blockIdx.y;
    const int L   = (seg == 0) ? LPP : LHH;
    const int* idx = ((seg == 0) ? idx_pre : idx_hyp) + b * L;

    __shared__ int sIdx[LHH];
    for (int i = threadIdx.x; i < L; i += blockDim.x) sIdx[i] = idx[i];
    __syncthreads();

    const int d = threadIdx.x;
    float acc0 = 0.f, acc1 = 0.f, acc2 = 0.f, acc3 = 0.f;
    // L is a multiple of 8 for both segments (256, 384)
    #pragma unroll 2
    for (int p = 0; p < L; p += 4) {
        const int r0 = sIdx[p + 0];
        const int r1 = sIdx[p + 1];
        const int r2 = sIdx[p + 2];
        const int r3 = sIdx[p + 3];
        acc0 += __ldg(&emb[r0 * DD + d]);
        acc1 += __ldg(&emb[r1 * DD + d]);
        acc2 += __ldg(&emb[r2 * DD + d]);
        acc3 += __ldg(&emb[r3 * DD + d]);
    }
    g_S[(b * 2 + seg) * DD + d] = (acc0 + acc1) + (acc2 + acc3);
}

// ---------------------------------------------------------------------------
// Kernel 2: fold W1 [2048,512] -> Wf [1024,512]
//   k < 512:        Wf[k][j] = W1[k][j]    + W1[k+1536][j]   (S_pre pair)
//   512 <= k <1024: Wf[k][j] = W1[k][j]    + W1[k+512][j]    (S_hyp pair)
// ---------------------------------------------------------------------------
__global__ __launch_bounds__(256) void k_fold(const float* __restrict__ W1)
{
    const int i = blockIdx.x * blockDim.x + threadIdx.x;   // 0 .. 1024*512-1
    if (i >= 2 * DD * DD) return;
    const int k = i >> 9;                                   // /512
    const int shift = (k < DD) ? (1536 * DD) : (512 * DD);
    g_Wf[i] = W1[i] + W1[i + shift];
}

// ---------------------------------------------------------------------------
// Kernel 3: hidden layer  H[64,512] = relu( S2[64,1024] @ Wf[1024,512] + b1 )
// grid (16 jtiles, 8 btiles); block = 256 threads = 32 j  x  8 b.
// S rows for the 8-b tile staged in shared (32 KB); warp has uniform b
// -> shared reads broadcast, W reads 128B-coalesced across the 32 j lanes.
// ---------------------------------------------------------------------------
__global__ __launch_bounds__(256) void k_hidden(
    const float* __restrict__ b1)
{
    __shared__ float sS[8][2 * DD];   // 8 * 1024 * 4 = 32 KB

    const int jt = blockIdx.x;        // 0..15
    const int bt = blockIdx.y;        // 0..7
    for (int i = threadIdx.x; i < 8 * 2 * DD; i += blockDim.x) {
        const int bb  = i >> 10;      // /1024
        const int off = i & 1023;
        sS[bb][off] = g_S[(bt * 8 + bb) * 2 * DD + off];
    }
    __syncthreads();

    const int tj = threadIdx.x & 31;      // j within tile
    const int tb = threadIdx.x >> 5;      // b within tile (uniform per warp)
    const int j  = jt * 32 + tj;

    const float* __restrict__ sp = sS[tb];
    float acc = b1[j];
    #pragma unroll 8
    for (int k = 0; k < 2 * DD; ++k) {
        acc += sp[k] * __ldg(&g_Wf[k * DD + j]);
    }
    acc = fmaxf(acc, 0.f);
    g_H[(bt * 8 + tb) * DD + j] = acc;
}

// ---------------------------------------------------------------------------
// Kernel 4: out[b] = sigmoid( b2 + dot(H[b,:], W2) ).  grid 64, block 256.
// ---------------------------------------------------------------------------
__global__ __launch_bounds__(256) void k_out(
    const float* __restrict__ W2,
    const float* __restrict__ b2,
    float* __restrict__ out)
{
    const int b = blockIdx.x;
    float acc = 0.f;
    for (int j = threadIdx.x; j < DD; j += 256)
        acc += g_H[b * DD + j] * W2[j];

    // warp reduce
    #pragma unroll
    for (int o = 16; o > 0; o >>= 1) acc += __shfl_xor_sync(~0u, acc, o);

    __shared__ float red[8];
    if ((threadIdx.x & 31) == 0) red[threadIdx.x >> 5] = acc;
    __syncthreads();
    if (threadIdx.x < 8) {
        acc = red[threadIdx.x];
        #pragma unroll
        for (int o = 4; o > 0; o >>= 1) acc += __shfl_xor_sync(0xffu, acc, o);
        if (threadIdx.x == 0) {
            const float z = acc + b2[0];
            out[b] = 1.f / (1.f + expf(-z));
        }
    }
}

// ---------------------------------------------------------------------------
extern "C" void kernel_launch(void* const* d_in, const int* in_sizes, int n_in,
                              void* d_out, int out_size)
{
    const int*   inputs_pre = (const int*)  d_in[0];
    const int*   inputs_hyp = (const int*)  d_in[1];
    // d_in[2], d_in[3]: masks (all ones) -> no-op
    const float* emb        = (const float*)d_in[4];
    const float* W1         = (const float*)d_in[5];
    const float* b1         = (const float*)d_in[6];
    const float* W2         = (const float*)d_in[7];
    const float* b2         = (const float*)d_in[8];
    float*       out        = (float*)d_out;

    // 1) embedding gather + per-sequence sums
    {
        dim3 grid(BB, 2);
        k_gather_sum<<<grid, 512>>>(inputs_pre, inputs_hyp, emb);
    }
    // 2) fold W1 -> Wf
    {
        const int n = 2 * DD * DD;
        k_fold<<<(n + 255) / 256, 256>>>(W1);
    }
    // 3) hidden layer GEMM + relu
    {
        dim3 grid(DD / 32, BB / 8);
        k_hidden<<<grid, 256>>>(b1);
    }
    // 4) final dot + sigmoid
    {
        k_out<<<BB, 256>>>(W2, b2, out);
    }
}

// round 2
// speedup vs baseline: 1.8894x; 1.8894x over previous
#include <cuda_runtime.h>

// B=64, LP=256, LH=384, D=512, VOCAB=50000
// Inputs: [0] inputs_pre i32[64,256], [1] inputs_hyp i32[64,384],
//         [2],[3] masks (all ones, unused), [4] emb f32[50000,512],
//         [5] W1 f32[2048,512], [6] b1 f32[512], [7] W2 f32[512,1], [8] b2 f32[1]
// Output: f32[64,1]
//
// Softmax-cancellation identity: sum_p pre_att = sum_h hyp, sum_h hyp_att = sum_p pre
// => pre_hyp[b] = [S_pre, S_hyp, S_hyp, S_pre], attention cancels exactly.
// Fold W1 accordingly: Wf[k] = W1[k] + W1[k+1536] (k<512), W1[k] + W1[k+512] (512<=k<1024).

#define BB   64
#define LPP  256
#define LHH  384
#define DD   512
#define KT   8          // k-split for hidden layer
#define KCH  (1024/KT)  // 128 k per chunk

__device__ float g_S [BB * 2 * DD];        // [b][seg][d]
__device__ float g_Wf[2 * DD * DD];        // folded W1 [1024,512]
__device__ float g_Hp[KT * BB * DD];       // hidden partials [kt][b][j]

// ---------------------------------------------------------------------------
// Kernel A: blocks 0..127 -> embedding gather+sum (LDG.128, high MLP)
//           blocks 128..159 -> fold W1 -> Wf
// ---------------------------------------------------------------------------
__global__ __launch_bounds__(512) void kA(
    const int* __restrict__ idx_pre,
    const int* __restrict__ idx_hyp,
    const float* __restrict__ emb,
    const float* __restrict__ W1)
{
    const int blk = blockIdx.x;
    if (blk < 128) {
        const int b   = blk >> 1;
        const int seg = blk & 1;
        const int L   = seg ? LHH : LPP;
        const int* idx = seg ? (idx_hyp + b * LHH) : (idx_pre + b * LPP);

        __shared__ int    sIdx[LHH];
        __shared__ float4 sRed[4][128];

        for (int i = threadIdx.x; i < L; i += 512) sIdx[i] = idx[i];
        __syncthreads();

        const int lane4 = threadIdx.x & 127;   // float4 lane within row
        const int slot  = threadIdx.x >> 7;    // 0..3 row slot
        const float4* __restrict__ emb4 = (const float4*)emb;

        float4 a0 = {0,0,0,0}, a1 = {0,0,0,0};
        // L/8 iterations (32 or 48), 2 independent chains, unroll 4 -> 8 loads in flight
        #pragma unroll 4
        for (int p = slot; p < L; p += 8) {
            const int r0 = sIdx[p];
            const int r1 = sIdx[p + 4];
            float4 v0 = __ldg(&emb4[r0 * 128 + lane4]);
            float4 v1 = __ldg(&emb4[r1 * 128 + lane4]);
            a0.x += v0.x; a0.y += v0.y; a0.z += v0.z; a0.w += v0.w;
            a1.x += v1.x; a1.y += v1.y; a1.z += v1.z; a1.w += v1.w;
        }
        a0.x += a1.x; a0.y += a1.y; a0.z += a1.z; a0.w += a1.w;
        sRed[slot][lane4] = a0;
        __syncthreads();
        if (slot == 0) {
            float4 t = sRed[0][lane4];
            float4 u = sRed[1][lane4];
            float4 v = sRed[2][lane4];
            float4 w = sRed[3][lane4];
            t.x += u.x + v.x + w.x;
            t.y += u.y + v.y + w.y;
            t.z += u.z + v.z + w.z;
            t.w += u.w + v.w + w.w;
            ((float4*)g_S)[(b * 2 + seg) * 128 + lane4] = t;
        }
    } else {
        // fold: 131072 float4 total, 32 blocks x 4096 each
        const int fb = blk - 128;
        const float4* __restrict__ W14 = (const float4*)W1;
        float4* __restrict__ Wf4 = (float4*)g_Wf;
        const int base = fb * 4096;
        #pragma unroll 4
        for (int t = base + threadIdx.x; t < base + 4096; t += 512) {
            const int k = t >> 7;                         // row (128 f4/row)
            const int shift = (k < DD) ? (1536 * 128) : (512 * 128);
            float4 a = __ldg(&W14[t]);
            float4 c = __ldg(&W14[t + shift]);
            a.x += c.x; a.y += c.y; a.z += c.z; a.w += c.w;
            Wf4[t] = a;
        }
    }
}

// ---------------------------------------------------------------------------
// Kernel B: hidden partials.  grid (jt=4, bt=8, kt=8), block 256 = 32 j4 x 8 b.
// Each block: partial H over 128-k chunk for (128 j, 8 b). Wf loaded as float4
// along j (coalesced 512B/warp), S chunk in smem (broadcast reads).
// ---------------------------------------------------------------------------
__global__ __launch_bounds__(256) void kB()
{
    __shared__ float sS[8][KCH];   // 8 b x 128 k = 4KB

    const int jt = blockIdx.x;     // 0..3
    const int bt = blockIdx.y;     // 0..7
    const int kt = blockIdx.z;     // 0..7

    for (int i = threadIdx.x; i < 8 * KCH; i += 256) {
        const int bb = i >> 7;
        const int kk = i & (KCH - 1);
        sS[bb][kk] = g_S[(bt * 8 + bb) * 2 * DD + kt * KCH + kk];
    }
    __syncthreads();

    const int tj = threadIdx.x & 31;    // j4 lane
    const int tb = threadIdx.x >> 5;    // b row (uniform per warp)
    const int j4 = jt * 32 + tj;        // float4 column index (0..127)

    const float4* __restrict__ Wp = (const float4*)g_Wf + (size_t)(kt * KCH) * 128 + j4;
    const float*  __restrict__ sp = sS[tb];

    float4 a0 = {0,0,0,0}, a1 = {0,0,0,0};
    #pragma unroll 8
    for (int k = 0; k < KCH; k += 2) {
        const float s0 = sp[k];
        const float s1 = sp[k + 1];
        float4 w0 = __ldg(Wp + (size_t)k * 128);
        float4 w1 = __ldg(Wp + (size_t)(k + 1) * 128);
        a0.x += s0 * w0.x; a0.y += s0 * w0.y; a0.z += s0 * w0.z; a0.w += s0 * w0.w;
        a1.x += s1 * w1.x; a1.y += s1 * w1.y; a1.z += s1 * w1.z; a1.w += s1 * w1.w;
    }
    a0.x += a1.x; a0.y += a1.y; a0.z += a1.z; a0.w += a1.w;

    ((float4*)g_Hp)[((kt * BB) + bt * 8 + tb) * 128 + j4] = a0;
}

// ---------------------------------------------------------------------------
// Kernel C: combine partials + bias -> relu -> dot W2 -> sigmoid. grid 64.
// ---------------------------------------------------------------------------
__global__ __launch_bounds__(256) void kC(
    const float* __restrict__ b1,
    const float* __restrict__ W2,
    const float* __restrict__ b2,
    float* __restrict__ out)
{
    const int b = blockIdx.x;
    float acc = 0.f;
    for (int j = threadIdx.x; j < DD; j += 256) {
        float h = b1[j];
        #pragma unroll
        for (int kt = 0; kt < KT; ++kt)
            h += g_Hp[(kt * BB + b) * DD + j];
        h = fmaxf(h, 0.f);
        acc += h * __ldg(&W2[j]);
    }
    #pragma unroll
    for (int o = 16; o > 0; o >>= 1) acc += __shfl_xor_sync(~0u, acc, o);

    __shared__ float red[8];
    if ((threadIdx.x & 31) == 0) red[threadIdx.x >> 5] = acc;
    __syncthreads();
    if (threadIdx.x < 8) {
        acc = red[threadIdx.x];
        #pragma unroll
        for (int o = 4; o > 0; o >>= 1) acc += __shfl_xor_sync(0xffu, acc, o);
        if (threadIdx.x == 0) {
            const float z = acc + b2[0];
            out[b] = 1.f / (1.f + expf(-z));
        }
    }
}

// ---------------------------------------------------------------------------
extern "C" void kernel_launch(void* const* d_in, const int* in_sizes, int n_in,
                              void* d_out, int out_size)
{
    const int*   inputs_pre = (const int*)  d_in[0];
    const int*   inputs_hyp = (const int*)  d_in[1];
    const float* emb        = (const float*)d_in[4];
    const float* W1         = (const float*)d_in[5];
    const float* b1         = (const float*)d_in[6];
    const float* W2         = (const float*)d_in[7];
    const float* b2         = (const float*)d_in[8];
    float*       out        = (float*)d_out;

    kA<<<160, 512>>>(inputs_pre, inputs_hyp, emb, W1);

    dim3 gB(4, 8, KT);
    kB<<<gB, 256>>>();

    kC<<<BB, 256>>>(b1, W2, b2, out);
}

// round 3
// speedup vs baseline: 2.0127x; 1.0653x over previous
#include <cuda_runtime.h>

// B=64, LP=256, LH=384, D=512, VOCAB=50000
// Inputs: [0] inputs_pre i32[64,256], [1] inputs_hyp i32[64,384],
//         [2],[3] masks (all ones, unused), [4] emb f32[50000,512],
//         [5] W1 f32[2048,512], [6] b1 f32[512], [7] W2 f32[512,1], [8] b2 f32[1]
// Output: f32[64,1]
//
// Softmax-cancellation: sum_p pre_att = sum_h hyp, sum_h hyp_att = sum_p pre
// => pre_hyp[b] = [S_pre, S_hyp, S_hyp, S_pre]; attention cancels exactly.
// Hidden layer uses folded weights on the fly:
//   k<512  : W1[k] + W1[k+1536]   (multiplies S_pre[k])
//   k>=512 : W1[k] + W1[k+512]    (multiplies S_hyp[k-512])

#define BB   64
#define DD   512
#define KT   8           // k-split for hidden layer
#define KCH  (1024/KT)   // 128 k per chunk
#define NCH  4           // gather chunks per sequence

__device__ float g_Sp[NCH * BB * 2 * DD];   // gather partials [chunk][b*2+seg][d]
__device__ float g_Hp[KT * BB * DD];        // hidden partials [kt][b][j]

// ---------------------------------------------------------------------------
// Kernel A: pure embedding gather+sum partials.
// grid = 512 blocks (b*2+seg)*4+chunk, block 512 = 128 f4-lanes x 4 row slots.
// pre: chunk = 64 rows, hyp: chunk = 96 rows.
// ---------------------------------------------------------------------------
__global__ __launch_bounds__(512) void kA(
    const int* __restrict__ idx_pre,
    const int* __restrict__ idx_hyp,
    const float* __restrict__ emb)
{
    const int blk   = blockIdx.x;
    const int chunk = blk & 3;
    const int bs    = blk >> 2;         // b*2+seg
    const int b     = bs >> 1;
    const int seg   = bs & 1;
    const int CL    = seg ? 96 : 64;
    const int* idx  = (seg ? (idx_hyp + b * 384) : (idx_pre + b * 256)) + chunk * CL;

    __shared__ int    sIdx[96];
    __shared__ float4 sRed[4][128];

    for (int i = threadIdx.x; i < CL; i += 512) sIdx[i] = idx[i];
    __syncthreads();

    const int lane4 = threadIdx.x & 127;
    const int slot  = threadIdx.x >> 7;
    const float4* __restrict__ emb4 = (const float4*)emb;

    float4 a0 = {0,0,0,0}, a1 = {0,0,0,0};
    // CL/8 iterations (8 or 12), 2 chains, unrolled -> 8 loads in flight/thread
    #pragma unroll 4
    for (int p = slot; p < CL; p += 8) {
        const int r0 = sIdx[p];
        const int r1 = sIdx[p + 4];
        float4 v0 = __ldg(&emb4[(size_t)r0 * 128 + lane4]);
        float4 v1 = __ldg(&emb4[(size_t)r1 * 128 + lane4]);
        a0.x += v0.x; a0.y += v0.y; a0.z += v0.z; a0.w += v0.w;
        a1.x += v1.x; a1.y += v1.y; a1.z += v1.z; a1.w += v1.w;
    }
    a0.x += a1.x; a0.y += a1.y; a0.z += a1.z; a0.w += a1.w;
    sRed[slot][lane4] = a0;
    __syncthreads();
    if (slot == 0) {
        float4 t = sRed[0][lane4];
        float4 u = sRed[1][lane4];
        float4 v = sRed[2][lane4];
        float4 w = sRed[3][lane4];
        t.x += u.x + v.x + w.x;
        t.y += u.y + v.y + w.y;
        t.z += u.z + v.z + w.z;
        t.w += u.w + v.w + w.w;
        ((float4*)g_Sp)[((size_t)chunk * 128 + bs) * 128 + lane4] = t;
    }
}

// ---------------------------------------------------------------------------
// Kernel B: hidden partials with on-the-fly W1 fold.
// grid (jt=4, bt=8, kt=8), block 256 = 32 j4-lanes x 8 b.
// smem stage combines the 4 gather partials (fixed order -> deterministic).
// ---------------------------------------------------------------------------
__global__ __launch_bounds__(256) void kB(const float* __restrict__ W1)
{
    __shared__ float sS[8][KCH];   // 8 b x 128 k

    const int jt = blockIdx.x;     // 0..3
    const int bt = blockIdx.y;     // 0..7
    const int kt = blockIdx.z;     // 0..7
    const int seg = (kt >= KT / 2) ? 1 : 0;

    // load + combine S partials: k global = kt*128+kk, d = k & 511
    for (int i = threadIdx.x; i < 8 * KCH; i += 256) {
        const int bb = i >> 7;
        const int kk = i & (KCH - 1);
        const int d  = (kt * KCH + kk) & (DD - 1);
        const int bs = (bt * 8 + bb) * 2 + seg;
        float s = g_Sp[(0 * BB * 2 + bs) * DD + d]
                + g_Sp[(1 * BB * 2 + bs) * DD + d]
                + g_Sp[(2 * BB * 2 + bs) * DD + d]
                + g_Sp[(3 * BB * 2 + bs) * DD + d];
        sS[bb][kk] = s;
    }
    __syncthreads();

    const int tj = threadIdx.x & 31;
    const int tb = threadIdx.x >> 5;      // uniform per warp
    const int j4 = jt * 32 + tj;          // float4 column (0..127)

    // W1 rows: k and k+shift; shift = 1536 (pre) or 512 (hyp), in f4 row units
    const size_t shift = (size_t)(seg ? 512 : 1536) * 128;
    const float4* __restrict__ Wp = (const float4*)W1 + (size_t)(kt * KCH) * 128 + j4;
    const float*  __restrict__ sp = sS[tb];

    float4 a0 = {0,0,0,0}, a1 = {0,0,0,0};
    #pragma unroll 8
    for (int k = 0; k < KCH; k += 2) {
        const float s0 = sp[k];
        const float s1 = sp[k + 1];
        const float4* p0 = Wp + (size_t)k * 128;
        const float4* p1 = Wp + (size_t)(k + 1) * 128;
        float4 w0a = __ldg(p0);
        float4 w0b = __ldg(p0 + shift);
        float4 w1a = __ldg(p1);
        float4 w1b = __ldg(p1 + shift);
        a0.x += s0 * (w0a.x + w0b.x); a0.y += s0 * (w0a.y + w0b.y);
        a0.z += s0 * (w0a.z + w0b.z); a0.w += s0 * (w0a.w + w0b.w);
        a1.x += s1 * (w1a.x + w1b.x); a1.y += s1 * (w1a.y + w1b.y);
        a1.z += s1 * (w1a.z + w1b.z); a1.w += s1 * (w1a.w + w1b.w);
    }
    a0.x += a1.x; a0.y += a1.y; a0.z += a1.z; a0.w += a1.w;

    ((float4*)g_Hp)[((size_t)(kt * BB) + bt * 8 + tb) * 128 + j4] = a0;
}

// ---------------------------------------------------------------------------
// Kernel C: combine partials + bias -> relu -> dot W2 -> sigmoid.
// grid 64, block 128 (one float4 column per thread).
// ---------------------------------------------------------------------------
__global__ __launch_bounds__(128) void kC(
    const float* __restrict__ b1,
    const float* __restrict__ W2,
    const float* __restrict__ b2,
    float* __restrict__ out)
{
    const int b  = blockIdx.x;
    const int j4 = threadIdx.x;   // 0..127

    float4 h = __ldg(&((const float4*)b1)[j4]);
    #pragma unroll
    for (int kt = 0; kt < KT; ++kt) {
        float4 p = ((const float4*)g_Hp)[((size_t)(kt * BB) + b) * 128 + j4];
        h.x += p.x; h.y += p.y; h.z += p.z; h.w += p.w;
    }
    h.x = fmaxf(h.x, 0.f); h.y = fmaxf(h.y, 0.f);
    h.z = fmaxf(h.z, 0.f); h.w = fmaxf(h.w, 0.f);

    float4 w = __ldg(&((const float4*)W2)[j4]);
    float acc = h.x * w.x + h.y * w.y + h.z * w.z + h.w * w.w;

    #pragma unroll
    for (int o = 16; o > 0; o >>= 1) acc += __shfl_xor_sync(~0u, acc, o);

    __shared__ float red[4];
    if ((threadIdx.x & 31) == 0) red[threadIdx.x >> 5] = acc;
    __syncthreads();
    if (threadIdx.x == 0) {
        const float z = red[0] + red[1] + red[2] + red[3] + b2[0];
        out[b] = 1.f / (1.f + expf(-z));
    }
}

// ---------------------------------------------------------------------------
extern "C" void kernel_launch(void* const* d_in, const int* in_sizes, int n_in,
                              void* d_out, int out_size)
{
    const int*   inputs_pre = (const int*)  d_in[0];
    const int*   inputs_hyp = (const int*)  d_in[1];
    const float* emb        = (const float*)d_in[4];
    const float* W1         = (const float*)d_in[5];
    const float* b1         = (const float*)d_in[6];
    const float* W2         = (const float*)d_in[7];
    const float* b2         = (const float*)d_in[8];
    float*       out        = (float*)d_out;

    kA<<<512, 512>>>(inputs_pre, inputs_hyp, emb);

    dim3 gB(4, 8, KT);
    kB<<<gB, 256>>>(W1);

    kC<<<BB, 128>>>(b1, W2, b2, out);
}

// round 4
// speedup vs baseline: 2.8030x; 1.3927x over previous
#include <cuda_runtime.h>

// B=64, LP=256, LH=384, D=512, VOCAB=50000
// Inputs: [0] inputs_pre i32[64,256], [1] inputs_hyp i32[64,384],
//         [2],[3] masks (ones, unused), [4] emb f32[50000,512],
//         [5] W1 f32[2048,512], [6] b1 f32[512], [7] W2 f32[512,1], [8] b2 f32[1]
// Output: f32[64,1]
//
// Softmax-cancellation: sum_p pre_att = sum_h hyp, sum_h hyp_att = sum_p pre
// => pre_hyp[b] = [S_pre, S_hyp, S_hyp, S_pre]; attention cancels exactly.
// Folded weights: Wf[k] = W1[k]+W1[k+1536] (k<512), W1[k]+W1[k+512] (512<=k<1024).

#define BB   64
#define DD   512
#define KT   16          // k-split for hidden layer
#define KCH  (1024/KT)   // 64 k per chunk
#define NCH  4           // gather chunks per sequence

__device__ float g_Sp[NCH * BB * 2 * DD];   // gather partials [chunk][b*2+seg][d]
__device__ float g_Wf[2 * DD * DD];         // folded W1 [1024,512]
__device__ float g_Hp[KT * BB * DD];        // hidden partials [kt][b][j]

// ---------------------------------------------------------------------------
// Kernel A: blocks 0..511  -> embedding gather+sum partials
//           blocks 512..543 -> fold W1 -> Wf
// Gather block: 512 thr = 128 f4-lanes x 4 row slots; slot owns a contiguous
// run of CL/4 rows; 2 chains x unroll 4 -> 8 LDG.128 in flight per thread.
// ---------------------------------------------------------------------------
__global__ __launch_bounds__(512, 2) void kA(
    const int* __restrict__ idx_pre,
    const int* __restrict__ idx_hyp,
    const float* __restrict__ emb,
    const float* __restrict__ W1)
{
    const int blk = blockIdx.x;
    if (blk < 512) {
        const int chunk = blk & 3;
        const int bs    = blk >> 2;        // b*2+seg
        const int b     = bs >> 1;
        const int seg   = bs & 1;
        const int CL    = seg ? 96 : 64;   // rows in this chunk
        const int* idx  = (seg ? (idx_hyp + b * 384) : (idx_pre + b * 256)) + chunk * CL;

        __shared__ int    sIdx[96];
        __shared__ float4 sRed[4][128];

        for (int i = threadIdx.x; i < CL; i += 512) sIdx[i] = idx[i];
        __syncthreads();

        const int lane4 = threadIdx.x & 127;
        const int slot  = threadIdx.x >> 7;
        const int Q     = CL >> 2;           // 16 or 24 rows per slot
        const int base  = slot * Q;
        const float4* __restrict__ emb4 = (const float4*)emb;

        float4 a0 = {0,0,0,0}, a1 = {0,0,0,0};
        #pragma unroll 4
        for (int p = 0; p < Q; p += 2) {
            const int r0 = sIdx[base + p];
            const int r1 = sIdx[base + p + 1];
            float4 v0 = __ldg(&emb4[(size_t)r0 * 128 + lane4]);
            float4 v1 = __ldg(&emb4[(size_t)r1 * 128 + lane4]);
            a0.x += v0.x; a0.y += v0.y; a0.z += v0.z; a0.w += v0.w;
            a1.x += v1.x; a1.y += v1.y; a1.z += v1.z; a1.w += v1.w;
        }
        a0.x += a1.x; a0.y += a1.y; a0.z += a1.z; a0.w += a1.w;
        sRed[slot][lane4] = a0;
        __syncthreads();
        if (slot == 0) {
            float4 t = sRed[0][lane4];
            float4 u = sRed[1][lane4];
            float4 v = sRed[2][lane4];
            float4 w = sRed[3][lane4];
            t.x += u.x + v.x + w.x;
            t.y += u.y + v.y + w.y;
            t.z += u.z + v.z + w.z;
            t.w += u.w + v.w + w.w;
            ((float4*)g_Sp)[((size_t)chunk * 128 + bs) * 128 + lane4] = t;
        }
    } else {
        // fold: 131072 f4 outputs, 32 blocks x 4096 each
        const int fb = blk - 512;
        const float4* __restrict__ W14 = (const float4*)W1;
        float4* __restrict__ Wf4 = (float4*)g_Wf;
        const int base = fb * 4096;
        #pragma unroll 4
        for (int t = base + threadIdx.x; t < base + 4096; t += 512) {
            const int k = t >> 7;                        // Wf row (128 f4/row)
            const int shift = (k < DD) ? (1536 * 128) : (512 * 128);
            float4 a = __ldg(&W14[t]);
            float4 c = __ldg(&W14[t + shift]);
            a.x += c.x; a.y += c.y; a.z += c.z; a.w += c.w;
            Wf4[t] = a;
        }
    }
}

// ---------------------------------------------------------------------------
// Kernel B: hidden partials. grid (jt=4, bt=8, kt=16), block 256 = 32 j4 x 8 b.
// smem stage combines the 4 gather partials (fixed order -> deterministic).
// Per thread: 64 LDG.128 of L2-resident Wf.
// ---------------------------------------------------------------------------
__global__ __launch_bounds__(256) void kB()
{
    __shared__ float sS[8][KCH];   // 8 b x 64 k

    const int jt  = blockIdx.x;    // 0..3
    const int bt  = blockIdx.y;    // 0..7
    const int kt  = blockIdx.z;    // 0..15
    const int seg = (kt >= KT / 2) ? 1 : 0;

    for (int i = threadIdx.x; i < 8 * KCH; i += 256) {
        const int bb = i / KCH;
        const int kk = i & (KCH - 1);
        const int d  = (kt * KCH + kk) & (DD - 1);
        const int bs = (bt * 8 + bb) * 2 + seg;
        float s = g_Sp[(0 * BB * 2 + bs) * DD + d]
                + g_Sp[(1 * BB * 2 + bs) * DD + d]
                + g_Sp[(2 * BB * 2 + bs) * DD + d]
                + g_Sp[(3 * BB * 2 + bs) * DD + d];
        sS[bb][kk] = s;
    }
    __syncthreads();

    const int tj = threadIdx.x & 31;
    const int tb = threadIdx.x >> 5;      // uniform per warp
    const int j4 = jt * 32 + tj;          // float4 column (0..127)

    const float4* __restrict__ Wp = (const float4*)g_Wf + (size_t)(kt * KCH) * 128 + j4;
    const float*  __restrict__ sp = sS[tb];

    float4 a0 = {0,0,0,0}, a1 = {0,0,0,0};
    #pragma unroll 8
    for (int k = 0; k < KCH; k += 2) {
        const float s0 = sp[k];
        const float s1 = sp[k + 1];
        float4 w0 = __ldg(Wp + (size_t)k * 128);
        float4 w1 = __ldg(Wp + (size_t)(k + 1) * 128);
        a0.x += s0 * w0.x; a0.y += s0 * w0.y; a0.z += s0 * w0.z; a0.w += s0 * w0.w;
        a1.x += s1 * w1.x; a1.y += s1 * w1.y; a1.z += s1 * w1.z; a1.w += s1 * w1.w;
    }
    a0.x += a1.x; a0.y += a1.y; a0.z += a1.z; a0.w += a1.w;

    ((float4*)g_Hp)[((size_t)(kt * BB) + bt * 8 + tb) * 128 + j4] = a0;
}

// ---------------------------------------------------------------------------
// Kernel C: combine 16 partials + bias -> relu -> dot W2 -> sigmoid.
// grid 64, block 128 (one float4 column per thread). 16 independent loads.
// ---------------------------------------------------------------------------
__global__ __launch_bounds__(128) void kC(
    const float* __restrict__ b1,
    const float* __restrict__ W2,
    const float* __restrict__ b2,
    float* __restrict__ out)
{
    const int b  = blockIdx.x;
    const int j4 = threadIdx.x;   // 0..127

    float4 h = __ldg(&((const float4*)b1)[j4]);
    #pragma unroll
    for (int kt = 0; kt < KT; ++kt) {
        float4 p = ((const float4*)g_Hp)[((size_t)(kt * BB) + b) * 128 + j4];
        h.x += p.x; h.y += p.y; h.z += p.z; h.w += p.w;
    }
    h.x = fmaxf(h.x, 0.f); h.y = fmaxf(h.y, 0.f);
    h.z = fmaxf(h.z, 0.f); h.w = fmaxf(h.w, 0.f);

    float4 w = __ldg(&((const float4*)W2)[j4]);
    float acc = h.x * w.x + h.y * w.y + h.z * w.z + h.w * w.w;

    #pragma unroll
    for (int o = 16; o > 0; o >>= 1) acc += __shfl_xor_sync(~0u, acc, o);

    __shared__ float red[4];
    if ((threadIdx.x & 31) == 0) red[threadIdx.x >> 5] = acc;
    __syncthreads();
    if (threadIdx.x == 0) {
        const float z = red[0] + red[1] + red[2] + red[3] + b2[0];
        out[b] = 1.f / (1.f + expf(-z));
    }
}

// ---------------------------------------------------------------------------
extern "C" void kernel_launch(void* const* d_in, const int* in_sizes, int n_in,
                              void* d_out, int out_size)
{
    const int*   inputs_pre = (const int*)  d_in[0];
    const int*   inputs_hyp = (const int*)  d_in[1];
    const float* emb        = (const float*)d_in[4];
    const float* W1         = (const float*)d_in[5];
    const float* b1         = (const float*)d_in[6];
    const float* W2         = (const float*)d_in[7];
    const float* b2         = (const float*)d_in[8];
    float*       out        = (float*)d_out;

    kA<<<544, 512>>>(inputs_pre, inputs_hyp, emb, W1);

    dim3 gB(4, 8, KT);
    kB<<<gB, 256>>>();

    kC<<<BB, 128>>>(b1, W2, b2, out);
}

// round 5
// speedup vs baseline: 3.0876x; 1.1015x over previous
#include <cuda_runtime.h>

// B=64, LP=256, LH=384, D=512, VOCAB=50000
// Inputs: [0] inputs_pre i32[64,256], [1] inputs_hyp i32[64,384],
//         [2],[3] masks (ones, unused), [4] emb f32[50000,512],
//         [5] W1 f32[2048,512], [6] b1 f32[512], [7] W2 f32[512,1], [8] b2 f32[1]
// Output: f32[64,1]
//
// Softmax-cancellation: sum_p pre_att = sum_h hyp, sum_h hyp_att = sum_p pre
// => pre_hyp[b] = [S_pre, S_hyp, S_hyp, S_pre]; attention cancels exactly.
// Folded weights: Wf[k] = W1[k]+W1[k+1536] (k<512), W1[k]+W1[k+512] (512<=k<1024).

#define BB   64
#define DD   512
#define KT   16          // k-split for hidden layer
#define KCH  (1024/KT)   // 64 k per chunk
#define NCH  4           // gather chunks per sequence

__device__ float g_Sp[NCH * BB * 2 * DD];   // gather partials [chunk][b*2+seg][d]
__device__ float g_Wf[2 * DD * DD];         // folded W1 [1024,512]
__device__ float g_Hp[KT * BB * DD];        // hidden partials [kt][b][j]

// ---------------------------------------------------------------------------
// Kernel A: blocks 0..511  -> embedding gather+sum partials (R3 recipe)
//           blocks 512..543 -> fold W1 -> Wf
// Gather block: 512 thr = 128 f4-lanes x 4 row slots, strided rows,
// 2 chains x unroll 4 -> 8 LDG.128 in flight per thread, regs ~32.
// ---------------------------------------------------------------------------
__global__ __launch_bounds__(512) void kA(
    const int* __restrict__ idx_pre,
    const int* __restrict__ idx_hyp,
    const float* __restrict__ emb,
    const float* __restrict__ W1)
{
    const int blk = blockIdx.x;
    if (blk < 512) {
        const int chunk = blk & 3;
        const int bs    = blk >> 2;        // b*2+seg
        const int b     = bs >> 1;
        const int seg   = bs & 1;
        const int CL    = seg ? 96 : 64;   // rows in this chunk
        const int* idx  = (seg ? (idx_hyp + b * 384) : (idx_pre + b * 256)) + chunk * CL;

        __shared__ int    sIdx[96];
        __shared__ float4 sRed[4][128];

        for (int i = threadIdx.x; i < CL; i += 512) sIdx[i] = idx[i];
        __syncthreads();

        const int lane4 = threadIdx.x & 127;
        const int slot  = threadIdx.x >> 7;
        const float4* __restrict__ emb4 = (const float4*)emb;

        float4 a0 = {0,0,0,0}, a1 = {0,0,0,0};
        // CL/8 iterations (8 or 12), 2 chains, unroll 4 -> 8 loads in flight
        #pragma unroll 4
        for (int p = slot; p < CL; p += 8) {
            const int r0 = sIdx[p];
            const int r1 = sIdx[p + 4];
            float4 v0 = __ldg(&emb4[(size_t)r0 * 128 + lane4]);
            float4 v1 = __ldg(&emb4[(size_t)r1 * 128 + lane4]);
            a0.x += v0.x; a0.y += v0.y; a0.z += v0.z; a0.w += v0.w;
            a1.x += v1.x; a1.y += v1.y; a1.z += v1.z; a1.w += v1.w;
        }
        a0.x += a1.x; a0.y += a1.y; a0.z += a1.z; a0.w += a1.w;
        sRed[slot][lane4] = a0;
        __syncthreads();
        if (slot == 0) {
            float4 t = sRed[0][lane4];
            float4 u = sRed[1][lane4];
            float4 v = sRed[2][lane4];
            float4 w = sRed[3][lane4];
            t.x += u.x + v.x + w.x;
            t.y += u.y + v.y + w.y;
            t.z += u.z + v.z + w.z;
            t.w += u.w + v.w + w.w;
            ((float4*)g_Sp)[((size_t)chunk * 128 + bs) * 128 + lane4] = t;
        }
    } else {
        // fold: 131072 f4 outputs, 32 blocks x 4096 each
        const int fb = blk - 512;
        const float4* __restrict__ W14 = (const float4*)W1;
        float4* __restrict__ Wf4 = (float4*)g_Wf;
        const int base = fb * 4096;
        #pragma unroll 4
        for (int t = base + threadIdx.x; t < base + 4096; t += 512) {
            const int k = t >> 7;                        // Wf row (128 f4/row)
            const int shift = (k < DD) ? (1536 * 128) : (512 * 128);
            float4 a = __ldg(&W14[t]);
            float4 c = __ldg(&W14[t + shift]);
            a.x += c.x; a.y += c.y; a.z += c.z; a.w += c.w;
            Wf4[t] = a;
        }
    }
}

// ---------------------------------------------------------------------------
// Kernel B: hidden partials. grid (jt=4, bt=8, kt=16), block 256 = 32 j4 x 8 b.
// smem stage combines the 4 gather partials (fixed order -> deterministic).
// Per thread: 64 LDG.128 of L2-resident Wf; 4 chains x unroll 4 -> 16 in flight.
// ---------------------------------------------------------------------------
__global__ __launch_bounds__(256) void kB()
{
    __shared__ float sS[8][KCH];   // 8 b x 64 k

    const int jt  = blockIdx.x;    // 0..3
    const int bt  = blockIdx.y;    // 0..7
    const int kt  = blockIdx.z;    // 0..15
    const int seg = (kt >= KT / 2) ? 1 : 0;

    for (int i = threadIdx.x; i < 8 * KCH; i += 256) {
        const int bb = i / KCH;
        const int kk = i & (KCH - 1);
        const int d  = (kt * KCH + kk) & (DD - 1);
        const int bs = (bt * 8 + bb) * 2 + seg;
        float s = g_Sp[(0 * BB * 2 + bs) * DD + d]
                + g_Sp[(1 * BB * 2 + bs) * DD + d]
                + g_Sp[(2 * BB * 2 + bs) * DD + d]
                + g_Sp[(3 * BB * 2 + bs) * DD + d];
        sS[bb][kk] = s;
    }
    __syncthreads();

    const int tj = threadIdx.x & 31;
    const int tb = threadIdx.x >> 5;      // uniform per warp
    const int j4 = jt * 32 + tj;          // float4 column (0..127)

    const float4* __restrict__ Wp = (const float4*)g_Wf + (size_t)(kt * KCH) * 128 + j4;
    const float*  __restrict__ sp = sS[tb];

    float4 a0 = {0,0,0,0}, a1 = {0,0,0,0}, a2 = {0,0,0,0}, a3 = {0,0,0,0};
    #pragma unroll 4
    for (int k = 0; k < KCH; k += 4) {
        const float s0 = sp[k];
        const float s1 = sp[k + 1];
        const float s2 = sp[k + 2];
        const float s3 = sp[k + 3];
        float4 w0 = __ldg(Wp + (size_t)(k + 0) * 128);
        float4 w1 = __ldg(Wp + (size_t)(k + 1) * 128);
        float4 w2 = __ldg(Wp + (size_t)(k + 2) * 128);
        float4 w3 = __ldg(Wp + (size_t)(k + 3) * 128);
        a0.x += s0 * w0.x; a0.y += s0 * w0.y; a0.z += s0 * w0.z; a0.w += s0 * w0.w;
        a1.x += s1 * w1.x; a1.y += s1 * w1.y; a1.z += s1 * w1.z; a1.w += s1 * w1.w;
        a2.x += s2 * w2.x; a2.y += s2 * w2.y; a2.z += s2 * w2.z; a2.w += s2 * w2.w;
        a3.x += s3 * w3.x; a3.y += s3 * w3.y; a3.z += s3 * w3.z; a3.w += s3 * w3.w;
    }
    a0.x += a1.x; a0.y += a1.y; a0.z += a1.z; a0.w += a1.w;
    a2.x += a3.x; a2.y += a3.y; a2.z += a3.z; a2.w += a3.w;
    a0.x += a2.x; a0.y += a2.y; a0.z += a2.z; a0.w += a2.w;

    ((float4*)g_Hp)[((size_t)(kt * BB) + bt * 8 + tb) * 128 + j4] = a0;
}

// ---------------------------------------------------------------------------
// Kernel C: combine 16 partials + bias -> relu -> dot W2 -> sigmoid.
// grid (64 b x 2 jhalf), block 64: one float4 column per thread.
// Per-(b) result reduced via atomic-free two-stage: each half-block computes
// partial dot, halves combined through shared within the same b via separate
// blocks -> instead keep one block per b but 128 threads (same as R4; fast).
// ---------------------------------------------------------------------------
__global__ __launch_bounds__(128) void kC(
    const float* __restrict__ b1,
    const float* __restrict__ W2,
    const float* __restrict__ b2,
    float* __restrict__ out)
{
    const int b  = blockIdx.x;
    const int j4 = threadIdx.x;   // 0..127

    float4 h = __ldg(&((const float4*)b1)[j4]);
    #pragma unroll
    for (int kt = 0; kt < KT; ++kt) {
        float4 p = ((const float4*)g_Hp)[((size_t)(kt * BB) + b) * 128 + j4];
        h.x += p.x; h.y += p.y; h.z += p.z; h.w += p.w;
    }
    h.x = fmaxf(h.x, 0.f); h.y = fmaxf(h.y, 0.f);
    h.z = fmaxf(h.z, 0.f); h.w = fmaxf(h.w, 0.f);

    float4 w = __ldg(&((const float4*)W2)[j4]);
    float acc = h.x * w.x + h.y * w.y + h.z * w.z + h.w * w.w;

    #pragma unroll
    for (int o = 16; o > 0; o >>= 1) acc += __shfl_xor_sync(~0u, acc, o);

    __shared__ float red[4];
    if ((threadIdx.x & 31) == 0) red[threadIdx.x >> 5] = acc;
    __syncthreads();
    if (threadIdx.x == 0) {
        const float z = red[0] + red[1] + red[2] + red[3] + b2[0];
        out[b] = 1.f / (1.f + expf(-z));
    }
}

// ---------------------------------------------------------------------------
extern "C" void kernel_launch(void* const* d_in, const int* in_sizes, int n_in,
                              void* d_out, int out_size)
{
    const int*   inputs_pre = (const int*)  d_in[0];
    const int*   inputs_hyp = (const int*)  d_in[1];
    const float* emb        = (const float*)d_in[4];
    const float* W1         = (const float*)d_in[5];
    const float* b1         = (const float*)d_in[6];
    const float* W2         = (const float*)d_in[7];
    const float* b2         = (const float*)d_in[8];
    float*       out        = (float*)d_out;

    kA<<<544, 512>>>(inputs_pre, inputs_hyp, emb, W1);

    dim3 gB(4, 8, KT);
    kB<<<gB, 256>>>();

    kC<<<BB, 128>>>(b1, W2, b2, out);
}

// round 7
// speedup vs baseline: 3.2938x; 1.0668x over previous
#include <cuda_runtime.h>

// B=64, LP=256, LH=384, D=512, VOCAB=50000
// Inputs: [0] inputs_pre i32[64,256], [1] inputs_hyp i32[64,384],
//         [2],[3] masks (ones, unused), [4] emb f32[50000,512],
//         [5] W1 f32[2048,512], [6] b1 f32[512], [7] W2 f32[512,1], [8] b2 f32[1]
// Output: f32[64,1]
//
// Softmax-cancellation: sum_p pre_att = sum_h hyp, sum_h hyp_att = sum_p pre
// => pre_hyp[b] = [S_pre, S_hyp, S_hyp, S_pre]; attention cancels exactly.
// Folded weights: Wf[k] = W1[k]+W1[k+1536] (k<512), W1[k]+W1[k+512] (512<=k<1024).
//
// Single persistent kernel, 272 blocks x 512 threads (2 blocks/SM guaranteed
// co-resident -> software grid barrier is safe). Monotonic barrier counters
// survive graph replays without reset.

#define BB    64
#define DD    512
#define KT    16          // k-split for hidden layer
#define KCH   (1024/KT)   // 64 k per chunk
#define NCH   4           // gather chunks per sequence
#define NBLK  272

__device__ float g_Sp[NCH * BB * 2 * DD];   // gather partials [chunk][b*2+seg][d]
__device__ float g_Wf[2 * DD * DD];         // folded W1 [1024,512]
__device__ float g_Hp[KT * BB * DD];        // hidden partials [kt][b][j]
__device__ unsigned g_c1, g_c2;             // barrier counters (monotonic)

// emb load with L2 evict-last priority via cache_hint policy (the direct
// .L2::evict_last qualifier is v8.b32/v4.b64-only on sm_103; the
// createpolicy + cache_hint form accepts v4.f32).
__device__ __forceinline__ float4 ldg_el(const float4* p, unsigned long long pol) {
    float4 v;
    asm("ld.global.nc.L2::cache_hint.v4.f32 {%0,%1,%2,%3}, [%4], %5;"
        : "=f"(v.x), "=f"(v.y), "=f"(v.z), "=f"(v.w) : "l"(p), "l"(pol));
    return v;
}

__device__ __forceinline__ unsigned long long mk_policy() {
    unsigned long long pol;
    asm("createpolicy.fractional.L2::evict_last.b64 %0, 1.0;" : "=l"(pol));
    return pol;
}

__device__ __forceinline__ void grid_sync(unsigned* c) {
    __syncthreads();
    if (threadIdx.x == 0) {
        __threadfence();
        unsigned old = atomicAdd(c, 1u);
        unsigned target = (old / NBLK + 1u) * NBLK;
        unsigned v;
        do {
            asm volatile("ld.acquire.gpu.u32 %0, [%1];" : "=r"(v) : "l"(c));
        } while (v < target);
    }
    __syncthreads();
}

__global__ __launch_bounds__(512, 2) void kFused(
    const int* __restrict__ idx_pre,
    const int* __restrict__ idx_hyp,
    const float* __restrict__ emb,
    const float* __restrict__ W1,
    const float* __restrict__ b1,
    const float* __restrict__ W2,
    const float* __restrict__ b2,
    float* __restrict__ out)
{
    __shared__ int    sIdx[2][96];
    __shared__ float4 sRed[2][2][128];
    __shared__ float  sS[2][8][KCH];
    __shared__ float  sred3[4][4];

    const int tid = threadIdx.x;
    const int h   = tid >> 8;       // half-block 0/1
    const int lt  = tid & 255;      // thread within half
    const int blk = blockIdx.x;

    // =====================================================================
    // Phase 1: blocks 0..255 gather (unit = blk*2+h, 512 units),
    //          blocks 256..271 fold W1 -> Wf (units 0..31)
    // =====================================================================
    if (blk < 256) {
        const int u     = blk * 2 + h;      // 0..511
        const int chunk = u & 3;
        const int bs    = u >> 2;           // b*2+seg
        const int b     = bs >> 1;
        const int seg   = bs & 1;
        const int CL    = seg ? 96 : 64;
        const int* idx  = (seg ? (idx_hyp + b * 384) : (idx_pre + b * 256)) + chunk * CL;

        for (int i = lt; i < CL; i += 256) sIdx[h][i] = idx[i];
        __syncthreads();

        const int lane4 = lt & 127;
        const int slot  = lt >> 7;          // 0/1
        const int Q     = CL >> 1;          // 32 or 48 rows per slot
        const int base  = slot * Q;
        const float4* __restrict__ emb4 = (const float4*)emb;
        const unsigned long long pol = mk_policy();

        float4 a0 = {0,0,0,0}, a1 = {0,0,0,0};
        #pragma unroll 4
        for (int p = 0; p < Q; p += 2) {
            const int r0 = sIdx[h][base + p];
            const int r1 = sIdx[h][base + p + 1];
            float4 v0 = ldg_el(&emb4[(size_t)r0 * 128 + lane4], pol);
            float4 v1 = ldg_el(&emb4[(size_t)r1 * 128 + lane4], pol);
            a0.x += v0.x; a0.y += v0.y; a0.z += v0.z; a0.w += v0.w;
            a1.x += v1.x; a1.y += v1.y; a1.z += v1.z; a1.w += v1.w;
        }
        a0.x += a1.x; a0.y += a1.y; a0.z += a1.z; a0.w += a1.w;
        sRed[h][slot][lane4] = a0;
        __syncthreads();
        if (slot == 0) {
            float4 t = sRed[h][0][lane4];
            float4 u2 = sRed[h][1][lane4];
            t.x += u2.x; t.y += u2.y; t.z += u2.z; t.w += u2.w;
            ((float4*)g_Sp)[((size_t)chunk * 128 + bs) * 128 + lane4] = t;
        }
    } else {
        // fold: 32 units (one per half), each 4096 f4 over 256 threads
        const int fu = (blk - 256) * 2 + h;     // 0..31
        const float4* __restrict__ W14 = (const float4*)W1;
        float4* __restrict__ Wf4 = (float4*)g_Wf;
        const int base = fu * 4096;
        #pragma unroll 4
        for (int t = base + lt; t < base + 4096; t += 256) {
            const int k = t >> 7;
            const int shift = (k < DD) ? (1536 * 128) : (512 * 128);
            float4 a = __ldg(&W14[t]);
            float4 c = __ldg(&W14[t + shift]);
            a.x += c.x; a.y += c.y; a.z += c.z; a.w += c.w;
            Wf4[t] = a;
        }
    }

    grid_sync(&g_c1);

    // =====================================================================
    // Phase 2: hidden partials. 512 half-block units over 544 halves.
    // unit: kt = u>>5, bt = (u>>2)&7, jt = u&3. Per thread: 64 LDG.128 of
    // L2-resident Wf, 4 chains.
    // =====================================================================
    {
        const int u2  = blk * 2 + h;
        const bool act = (u2 < 512);
        int kt = 0, bt = 0, jt = 0, seg = 0;
        if (act) {
            kt  = u2 >> 5;
            bt  = (u2 >> 2) & 7;
            jt  = u2 & 3;
            seg = (kt >= KT / 2) ? 1 : 0;
            for (int i = lt; i < 8 * KCH; i += 256) {
                const int bb = i / KCH;
                const int kk = i & (KCH - 1);
                const int d  = (kt * KCH + kk) & (DD - 1);
                const int bs = (bt * 8 + bb) * 2 + seg;
                float s = g_Sp[(0 * BB * 2 + bs) * DD + d]
                        + g_Sp[(1 * BB * 2 + bs) * DD + d]
                        + g_Sp[(2 * BB * 2 + bs) * DD + d]
                        + g_Sp[(3 * BB * 2 + bs) * DD + d];
                sS[h][bb][kk] = s;
            }
        }
        __syncthreads();
        if (act) {
            const int tj = lt & 31;
            const int tb = lt >> 5;
            const int j4 = jt * 32 + tj;

            const float4* __restrict__ Wp = (const float4*)g_Wf + (size_t)(kt * KCH) * 128 + j4;
            const float*  __restrict__ sp = sS[h][tb];

            float4 a0 = {0,0,0,0}, a1 = {0,0,0,0}, a2 = {0,0,0,0}, a3 = {0,0,0,0};
            #pragma unroll 4
            for (int k = 0; k < KCH; k += 4) {
                const float s0 = sp[k];
                const float s1 = sp[k + 1];
                const float s2 = sp[k + 2];
                const float s3 = sp[k + 3];
                float4 w0 = __ldg(Wp + (size_t)(k + 0) * 128);
                float4 w1 = __ldg(Wp + (size_t)(k + 1) * 128);
                float4 w2 = __ldg(Wp + (size_t)(k + 2) * 128);
                float4 w3 = __ldg(Wp + (size_t)(k + 3) * 128);
                a0.x += s0 * w0.x; a0.y += s0 * w0.y; a0.z += s0 * w0.z; a0.w += s0 * w0.w;
                a1.x += s1 * w1.x; a1.y += s1 * w1.y; a1.z += s1 * w1.z; a1.w += s1 * w1.w;
                a2.x += s2 * w2.x; a2.y += s2 * w2.y; a2.z += s2 * w2.z; a2.w += s2 * w2.w;
                a3.x += s3 * w3.x; a3.y += s3 * w3.y; a3.z += s3 * w3.z; a3.w += s3 * w3.w;
            }
            a0.x += a1.x; a0.y += a1.y; a0.z += a1.z; a0.w += a1.w;
            a2.x += a3.x; a2.y += a3.y; a2.z += a3.z; a2.w += a3.w;
            a0.x += a2.x; a0.y += a2.y; a0.z += a2.z; a0.w += a2.w;

            ((float4*)g_Hp)[((size_t)(kt * BB) + bt * 8 + tb) * 128 + j4] = a0;
        }
    }

    grid_sync(&g_c2);

    // =====================================================================
    // Phase 3: combine 16 partials + bias -> relu -> dot W2 -> sigmoid.
    // Blocks 0..15, 4 b's per block (128 threads each).
    // =====================================================================
    if (blk < 16) {
        const int g  = tid >> 7;          // group 0..3
        const int b  = blk * 4 + g;
        const int j4 = tid & 127;

        float4 hh = __ldg(&((const float4*)b1)[j4]);
        #pragma unroll
        for (int kt = 0; kt < KT; ++kt) {
            float4 p = ((const float4*)g_Hp)[((size_t)(kt * BB) + b) * 128 + j4];
            hh.x += p.x; hh.y += p.y; hh.z += p.z; hh.w += p.w;
        }
        hh.x = fmaxf(hh.x, 0.f); hh.y = fmaxf(hh.y, 0.f);
        hh.z = fmaxf(hh.z, 0.f); hh.w = fmaxf(hh.w, 0.f);

        float4 w = __ldg(&((const float4*)W2)[j4]);
        float acc = hh.x * w.x + hh.y * w.y + hh.z * w.z + hh.w * w.w;

        #pragma unroll
        for (int o = 16; o > 0; o >>= 1) acc += __shfl_xor_sync(~0u, acc, o);

        if ((j4 & 31) == 0) sred3[g][(j4 >> 5)] = acc;
        __syncthreads();
        if (j4 == 0) {
            const float z = sred3[g][0] + sred3[g][1] + sred3[g][2] + sred3[g][3] + b2[0];
            out[b] = 1.f / (1.f + expf(-z));
        }
    }
}

// ---------------------------------------------------------------------------
extern "C" void kernel_launch(void* const* d_in, const int* in_sizes, int n_in,
                              void* d_out, int out_size)
{
    const int*   inputs_pre = (const int*)  d_in[0];
    const int*   inputs_hyp = (const int*)  d_in[1];
    const float* emb        = (const float*)d_in[4];
    const float* W1         = (const float*)d_in[5];
    const float* b1         = (const float*)d_in[6];
    const float* W2         = (const float*)d_in[7];
    const float* b2         = (const float*)d_in[8];
    float*       out        = (float*)d_out;

    kFused<<<NBLK, 512>>>(inputs_pre, inputs_hyp, emb, W1, b1, W2, b2, out);
}